// round 2
// baseline (speedup 1.0000x reference)
#include <cuda_runtime.h>
#include <cstdint>

// ---------------------------------------------------------------------------
// Problem constants
//   x:       (32, 512, 56, 56) f32
//   bn_*:    (1024,) f32
//   conv_w:  (256, 1024) f32
//   out:     (32, 256, 28, 28) f32
//
// Rewrite:  pool(W . relu(bn(cat))) == W . pool(relu(bn(cat)))
//   hbar[c2][b][ij]  (K-major A^T, M = b*784+ij = 25088, K = 1024)
//   out[b][n][ij] = sum_k hbar[k][b*784+ij] * conv_w[n][k]
// ---------------------------------------------------------------------------

#define PO 784         // 28*28
#define M_TOT 25088    // 32*784
#define K_TOT 1024
#define N_TOT 256
#define TOT_H (1024 * 32 * 784)

__device__ float g_hbar[25690112];   // [1024][32][784]  = A^T [K][M]
__device__ float g_wt[262144];       // [1024][256]      = W^T [K][N]

// resample map: p//7*6 + min(p%7,5), then +4 for the crop offset
__device__ __forceinline__ int rmap(int p) {
    int q = p / 7;
    int r = p - q * 7;
    return q * 6 + (r < 5 ? r : 5) + 4;
}

// ---------------------------------------------------------------------------
// Pass 0: transpose conv_w [256][1024] -> g_wt [1024][256]
// ---------------------------------------------------------------------------
__global__ void transW_kernel(const float* __restrict__ w) {
    int e = blockIdx.x * 256 + threadIdx.x;
    if (e < 262144) {
        int n = e & 255;
        int k = e >> 8;
        g_wt[e] = w[n * 1024 + k];
    }
}

// ---------------------------------------------------------------------------
// Pass 1: fused gather + BN + ReLU + 2x2 avg pool -> g_hbar [c2][b][ij]
// ---------------------------------------------------------------------------
__global__ void pass1_kernel(const float* __restrict__ x,
                             const float* __restrict__ gamma,
                             const float* __restrict__ beta,
                             const float* __restrict__ mean,
                             const float* __restrict__ var) {
    int e = blockIdx.x * 256 + threadIdx.x;
    if (e >= TOT_H) return;
    int ij = e % PO;
    int t  = e / PO;
    int b  = t & 31;
    int c2 = t >> 5;
    int i = ij / 28;
    int j = ij - i * 28;

    float inv  = gamma[c2] * rsqrtf(var[c2] + 1e-5f);
    float bias = fmaf(-mean[c2], inv, beta[c2]);

    const float* xp = x + (size_t)(b * 512 + (c2 & 511)) * 3136;

    float v00, v01, v10, v11;
    if (c2 < 512) {
        // direct channel: rows 2i, 2i+1, cols 2j, 2j+1 -> two float2 loads
        float2 a0 = *(const float2*)(xp + (2 * i) * 56 + 2 * j);
        float2 a1 = *(const float2*)(xp + (2 * i + 1) * 56 + 2 * j);
        v00 = a0.x; v01 = a0.y; v10 = a1.x; v11 = a1.y;
    } else {
        // upsampled channel: gather through the resample map
        int r0 = rmap(2 * i), r1 = rmap(2 * i + 1);
        int q0 = rmap(2 * j), q1 = rmap(2 * j + 1);
        v00 = xp[r0 * 56 + q0]; v01 = xp[r0 * 56 + q1];
        v10 = xp[r1 * 56 + q0]; v11 = xp[r1 * 56 + q1];
    }
    float s = fmaxf(fmaf(v00, inv, bias), 0.0f)
            + fmaxf(fmaf(v01, inv, bias), 0.0f)
            + fmaxf(fmaf(v10, inv, bias), 0.0f)
            + fmaxf(fmaf(v11, inv, bias), 0.0f);
    g_hbar[e] = 0.25f * s;
}

// ---------------------------------------------------------------------------
// Pass 2: GEMM  out[m][n] = sum_k A^T[k][m] * W^T[k][n]
// fp32 via packed fma.rn.f32x2 (2x the 3-reg FFMA rate on sm_103a)
// BM=128, BN=64, BK=16, 256 threads, per-thread 8(m) x 4(n) as 4 m-pairs.
// ---------------------------------------------------------------------------
__device__ __forceinline__ unsigned long long dup2(float f) {
    unsigned u = __float_as_uint(f);
    unsigned long long r;
    asm("mov.b64 %0, {%1, %1};" : "=l"(r) : "r"(u));
    return r;
}
__device__ __forceinline__ void fma2(unsigned long long& d,
                                     unsigned long long a,
                                     unsigned long long b) {
    asm("fma.rn.f32x2 %0, %1, %2, %0;" : "+l"(d) : "l"(a), "l"(b));
}
__device__ __forceinline__ float lo32(unsigned long long v) {
    return __uint_as_float((unsigned)(v & 0xffffffffu));
}
__device__ __forceinline__ float hi32(unsigned long long v) {
    return __uint_as_float((unsigned)(v >> 32));
}

#define BM 128
#define BN 64
#define BK 16
#define NKT 64   // 1024 / 16

__global__ __launch_bounds__(256, 2) void gemm_kernel(float* __restrict__ out) {
    __shared__ float As[BK][BM];   // 8 KB
    __shared__ float Bs[BK][BN];   // 4 KB

    const int m0  = blockIdx.x * BM;
    const int n0  = blockIdx.y * BN;
    const int tid = threadIdx.x;
    const int tx  = tid & 15;   // m micro-index (16 threads cover 128 rows as 2 groups)
    const int ty  = tid >> 4;   // n micro-index (16 threads cover 64 cols)

    // global tile-load assignments (all fully coalesced, K-major sources)
    const int a_kr = tid >> 5;          // 0..7 (also +8)
    const int a_lc = (tid & 31) << 2;   // float4 column in [0,128)
    const int b_kr = tid >> 4;          // 0..15
    const int b_lc = (tid & 15) << 2;   // float4 column in [0,64)

    const float* Ag = g_hbar + (size_t)a_kr * M_TOT + m0 + a_lc;
    const float* Bg = g_wt   + (size_t)b_kr * N_TOT + n0 + b_lc;

    unsigned long long acc[4][4];
#pragma unroll
    for (int i = 0; i < 4; ++i)
#pragma unroll
        for (int j = 0; j < 4; ++j) acc[i][j] = 0ULL;

    // prefetch tile 0 into registers
    float4 pa0 = *(const float4*)(Ag);
    float4 pa1 = *(const float4*)(Ag + 8 * M_TOT);
    float4 pb  = *(const float4*)(Bg);

    for (int kt = 0; kt < NKT; ++kt) {
        // commit prefetched tile to smem
        *(float4*)&As[a_kr][a_lc]     = pa0;
        *(float4*)&As[a_kr + 8][a_lc] = pa1;
        *(float4*)&Bs[b_kr][b_lc]     = pb;
        __syncthreads();

        // issue next tile's global loads (overlap with compute below)
        if (kt + 1 < NKT) {
            const float* Ag2 = Ag + (size_t)(kt + 1) * BK * M_TOT;
            pa0 = *(const float4*)(Ag2);
            pa1 = *(const float4*)(Ag2 + 8 * M_TOT);
            pb  = *(const float4*)(Bg + (size_t)(kt + 1) * BK * N_TOT);
        }

#pragma unroll
        for (int kk = 0; kk < BK; ++kk) {
            // a: two conflict-free LDS.128, natural (m,m+1) pairs
            ulonglong2 a0 = *(const ulonglong2*)&As[kk][tx * 4];
            ulonglong2 a1 = *(const ulonglong2*)&As[kk][64 + tx * 4];
            // b: one broadcast LDS.128, duplicate into (b,b) on the ALU pipe
            float4 bf = *(const float4*)&Bs[kk][ty * 4];
            unsigned long long b0 = dup2(bf.x);
            unsigned long long b1 = dup2(bf.y);
            unsigned long long b2 = dup2(bf.z);
            unsigned long long b3 = dup2(bf.w);

            fma2(acc[0][0], a0.x, b0); fma2(acc[0][1], a0.x, b1);
            fma2(acc[0][2], a0.x, b2); fma2(acc[0][3], a0.x, b3);
            fma2(acc[1][0], a0.y, b0); fma2(acc[1][1], a0.y, b1);
            fma2(acc[1][2], a0.y, b2); fma2(acc[1][3], a0.y, b3);
            fma2(acc[2][0], a1.x, b0); fma2(acc[2][1], a1.x, b1);
            fma2(acc[2][2], a1.x, b2); fma2(acc[2][3], a1.x, b3);
            fma2(acc[3][0], a1.y, b0); fma2(acc[3][1], a1.y, b1);
            fma2(acc[3][2], a1.y, b2); fma2(acc[3][3], a1.y, b3);
        }
        __syncthreads();
    }

    // epilogue: out[b][n][ij], vectorized float4 along m (784 % 4 == 0 so a
    // 4-aligned m group never crosses a batch/ij row boundary)
    const int mA  = m0 + tx * 4;
    const int mB  = mA + 64;
    const int bA  = mA / 784, ijA = mA - bA * 784;
    const int bB  = mB / 784, ijB = mB - bB * 784;
#pragma unroll
    for (int j = 0; j < 4; ++j) {
        int n = n0 + ty * 4 + j;
        float4 r0 = make_float4(lo32(acc[0][j]), hi32(acc[0][j]),
                                lo32(acc[1][j]), hi32(acc[1][j]));
        float4 r1 = make_float4(lo32(acc[2][j]), hi32(acc[2][j]),
                                lo32(acc[3][j]), hi32(acc[3][j]));
        *(float4*)&out[((size_t)bA * 256 + n) * 784 + ijA] = r0;
        *(float4*)&out[((size_t)bB * 256 + n) * 784 + ijB] = r1;
    }
}

// ---------------------------------------------------------------------------
extern "C" void kernel_launch(void* const* d_in, const int* in_sizes, int n_in,
                              void* d_out, int out_size) {
    (void)in_sizes; (void)n_in; (void)out_size;
    const float* x     = (const float*)d_in[0];
    const float* gamma = (const float*)d_in[1];
    const float* beta  = (const float*)d_in[2];
    const float* mean  = (const float*)d_in[3];
    const float* var   = (const float*)d_in[4];
    const float* w     = (const float*)d_in[5];
    float* out = (float*)d_out;

    transW_kernel<<<1024, 256>>>(w);
    pass1_kernel<<<(TOT_H + 255) / 256, 256>>>(x, gamma, beta, mean, var);
    dim3 g(M_TOT / BM, N_TOT / BN);   // (196, 4)
    gemm_kernel<<<g, 256>>>(out);
}